// round 13
// baseline (speedup 1.0000x reference)
#include <cuda_runtime.h>
#include <cuda_fp16.h>
#include <cstdint>

// Problem constants (RestGCNEqualHidden): N=50000, F=H=128, C=40, E=800000
#define MAXN 50016
#define MAXE 800032
#define FDIM 128
#define CDIM 40

// Scratch (device globals -- no allocation allowed)
__device__ int   g_is64;
__device__ int   g_src [MAXE];
__device__ int   g_dst [MAXE];
__device__ int   g_deg [MAXN];
__device__ float g_dinv[MAXN];
__device__ __align__(16) __half g_g1h[(size_t)MAXN * FDIM];  // fp16 msgs L1
__device__ __align__(16) float  g_agg1[(size_t)MAXN * FDIM]; // fp32 accum
__device__ __align__(16) __half g_g2h[(size_t)MAXN * CDIM];  // fp16 msgs L2

__device__ __forceinline__ void red_add_v4(float* addr, float4 v) {
    asm volatile("red.global.add.v4.f32 [%0], {%1,%2,%3,%4};"
                 :: "l"(addr), "f"(v.x), "f"(v.y), "f"(v.z), "f"(v.w)
                 : "memory");
}

__device__ __forceinline__ uint32_t f2tf(float f) {
    uint32_t u;
    asm("cvt.rna.tf32.f32 %0, %1;" : "=r"(u) : "f"(f));
    return u;
}
__device__ __forceinline__ uint4 f2tf4(float4 v) {
    uint4 o;
    o.x = f2tf(v.x); o.y = f2tf(v.y); o.z = f2tf(v.z); o.w = f2tf(v.w);
    return o;
}

// ---------------- dtype detect: int64 edges have zero high words ------------
__global__ void detect_kernel(const int* __restrict__ ei32) {
    if (threadIdx.x == 0 && blockIdx.x == 0) {
        int is64 = 1;
        for (int i = 1; i < 256; i += 2)
            if (ei32[i] != 0) { is64 = 0; break; }
        g_is64 = is64;
    }
}

// -------- convert edges to int32 + degree histogram (2 edges/thread) --------
__global__ void convert_kernel(const void* __restrict__ ei, int E) {
    int i = blockIdx.x * blockDim.x + threadIdx.x;   // pair index
    int e0 = i * 2;
    if (e0 >= E) return;
    int s0, d0, s1 = -1, d1 = -1;
    bool two = (e0 + 1 < E);
    if (g_is64) {
        const long long* p = (const long long*)ei;
        longlong2 sv = *((const longlong2*)(p + e0));
        longlong2 dv = *((const longlong2*)(p + (size_t)E + e0));
        s0 = (int)sv.x; d0 = (int)dv.x;
        if (two) { s1 = (int)sv.y; d1 = (int)dv.y; }
    } else {
        const int* p = (const int*)ei;
        int2 sv = *((const int2*)(p + e0));
        int2 dv = *((const int2*)(p + E + e0));
        s0 = sv.x; d0 = dv.x;
        if (two) { s1 = sv.y; d1 = dv.y; }
    }
    g_src[e0] = s0; g_dst[e0] = d0;
    atomicAdd(&g_deg[d0], 1);
    if (two) {
        g_src[e0 + 1] = s1; g_dst[e0 + 1] = d1;
        atomicAdd(&g_deg[d1], 1);
    }
}

__global__ void dinv_kernel(int N) {
    int i = blockIdx.x * blockDim.x + threadIdx.x;
    if (i < N) g_dinv[i] = rsqrtf((float)g_deg[i] + 1.0f);  // +1 self loop
}

// ------- GEMM1 (tf32 mma.sync): agg1 = (x @ W1)*dinv ; g1h = fp16(same) -----
// smem holds PRE-CONVERTED tf32 (uint32) -> mainloop is pure LDS + MMA.
// 256 threads = 8 warps (2x4), block tile 128x128, K split in 2 chunks of 64.
#define SXP 68     // sX row stride (pad 4)
#define SWP 136    // sW row stride (pad 8 -> conflict-free B lds)
__global__ __launch_bounds__(256, 2)
void gemm1_kernel(const float* __restrict__ x,
                  const float* __restrict__ W, int N) {
    extern __shared__ uint32_t smu[];
    uint32_t* sX = smu;                 // 128 x SXP  (tf32 bits)
    uint32_t* sW = smu + 128 * SXP;     // 64 x SWP   (tf32 bits)
    int tid  = threadIdx.x;
    int row0 = blockIdx.x * 128;

    int warp  = tid >> 5;
    int lane  = tid & 31;
    int warpM = warp >> 2;           // 0..1  (64 rows each)
    int warpN = warp & 3;            // 0..3  (32 cols each)
    int g   = lane >> 2;             // 0..7
    int tig = lane & 3;              // 0..3

    float acc[4][4][4];
#pragma unroll
    for (int mi = 0; mi < 4; mi++)
#pragma unroll
        for (int ni = 0; ni < 4; ni++)
#pragma unroll
            for (int c = 0; c < 4; c++) acc[mi][ni][c] = 0.f;

    for (int chunk = 0; chunk < 2; chunk++) {
        int kbase = chunk * 64;
        // load W rows [kbase, kbase+64) x 128 cols, convert to tf32 once
#pragma unroll
        for (int i = 0; i < 8; i++) {
            int f = tid + i * 256;          // [0, 2048)
            int kr = f >> 5, c4 = f & 31;
            float4 v = ((const float4*)W)[(size_t)(kbase + kr) * 32 + c4];
            *((uint4*)(sW + kr * SWP + c4 * 4)) = f2tf4(v);
        }
        // load x rows x cols [kbase, kbase+64), convert to tf32 once
#pragma unroll
        for (int i = 0; i < 8; i++) {
            int f = tid + i * 256;          // [0, 2048)
            int r = f >> 4, c4 = f & 15;    // 16 float4 per row
            float4 v = make_float4(0.f, 0.f, 0.f, 0.f);
            if (row0 + r < N)
                v = ((const float4*)x)[(size_t)(row0 + r) * 32 + (kbase >> 2) + c4];
            *((uint4*)(sX + r * SXP + c4 * 4)) = f2tf4(v);
        }
        __syncthreads();

#pragma unroll
        for (int k0 = 0; k0 < 64; k0 += 8) {
            uint32_t a[4][4];
#pragma unroll
            for (int mi = 0; mi < 4; mi++) {
                int r = warpM * 64 + mi * 16 + g;
                a[mi][0] = sX[(r)     * SXP + k0 + tig];
                a[mi][1] = sX[(r + 8) * SXP + k0 + tig];
                a[mi][2] = sX[(r)     * SXP + k0 + 4 + tig];
                a[mi][3] = sX[(r + 8) * SXP + k0 + 4 + tig];
            }
            uint32_t b[4][2];
#pragma unroll
            for (int ni = 0; ni < 4; ni++) {
                int col = warpN * 32 + ni * 8 + g;
                b[ni][0] = sW[(k0 + tig)     * SWP + col];
                b[ni][1] = sW[(k0 + 4 + tig) * SWP + col];
            }
#pragma unroll
            for (int mi = 0; mi < 4; mi++)
#pragma unroll
                for (int ni = 0; ni < 4; ni++)
                    asm volatile(
                        "mma.sync.aligned.m16n8k8.row.col.f32.tf32.tf32.f32 "
                        "{%0,%1,%2,%3},{%4,%5,%6,%7},{%8,%9},{%0,%1,%2,%3};"
                        : "+f"(acc[mi][ni][0]), "+f"(acc[mi][ni][1]),
                          "+f"(acc[mi][ni][2]), "+f"(acc[mi][ni][3])
                        : "r"(a[mi][0]), "r"(a[mi][1]), "r"(a[mi][2]), "r"(a[mi][3]),
                          "r"(b[ni][0]), "r"(b[ni][1]));
        }
        __syncthreads();
    }

    // epilogue: scale by dinv[row]; fp32 -> agg1 (self loop), fp16 -> g1h
#pragma unroll
    for (int mi = 0; mi < 4; mi++) {
        int r0 = row0 + warpM * 64 + mi * 16 + g;
        int r1 = r0 + 8;
        float dv0 = (r0 < N) ? g_dinv[r0] : 0.f;
        float dv1 = (r1 < N) ? g_dinv[r1] : 0.f;
#pragma unroll
        for (int ni = 0; ni < 4; ni++) {
            int col = warpN * 32 + ni * 8 + 2 * tig;
            if (r0 < N) {
                float2 o = make_float2(acc[mi][ni][0] * dv0, acc[mi][ni][1] * dv0);
                *((float2*)(g_agg1 + (size_t)r0 * 128 + col)) = o;
                *((__half2*)(g_g1h + (size_t)r0 * 128 + col)) = __float22half2_rn(o);
            }
            if (r1 < N) {
                float2 o = make_float2(acc[mi][ni][2] * dv1, acc[mi][ni][3] * dv1);
                *((float2*)(g_agg1 + (size_t)r1 * 128 + col)) = o;
                *((__half2*)(g_g1h + (size_t)r1 * 128 + col)) = __float22half2_rn(o);
            }
        }
    }
}

// ------- edge scatter layer 1: agg1[dst] += fp32(g1h[src]) ------------------
// 2 edges per warp: lanes 0-15 edge 2w, lanes 16-31 edge 2w+1; uint4 gathers.
__global__ void scatter1_kernel(int E) {
    int w = blockIdx.x * 8 + (threadIdx.x >> 5);
    int lane = threadIdx.x & 31;
    int e = w * 2 + (lane >> 4);
    int l = lane & 15;                 // 16 lanes x 8 fp16 = 128
    if (e >= E) return;
    int s = g_src[e];
    int d = g_dst[e];
    uint4 raw = *((const uint4*)(g_g1h + (size_t)s * 128 + l * 8));
    float2 f0 = __half22float2(*reinterpret_cast<__half2*>(&raw.x));
    float2 f1 = __half22float2(*reinterpret_cast<__half2*>(&raw.y));
    float2 f2 = __half22float2(*reinterpret_cast<__half2*>(&raw.z));
    float2 f3 = __half22float2(*reinterpret_cast<__half2*>(&raw.w));
    float* dst = &g_agg1[(size_t)d * FDIM + l * 8];
    red_add_v4(dst,     make_float4(f0.x, f0.y, f1.x, f1.y));
    red_add_v4(dst + 4, make_float4(f2.x, f2.y, f3.x, f3.y));
}

// ---- GEMM2 (tf32 mma) with fused layer-1 epilogue in the load stage --------
// x1c = relu(agg1*dinv + b1) + x computed on the fly -> tf32 into smem, then
// self-loop term of conv2 goes STRAIGHT to d_out: out = acc*dinv^2 + b2;
// fp16 pre-scaled messages g2h = fp16(acc*dinv) for scatter2.
#define SX2P 132   // sX row stride
#define SW2P 44    // sW row stride
__global__ __launch_bounds__(256, 2)
void gemm2_kernel(const float* __restrict__ W,
                  const float4* __restrict__ x,
                  const float* __restrict__ b1,
                  const float* __restrict__ b2,
                  float* __restrict__ out, int N) {
    extern __shared__ uint32_t smu[];
    uint32_t* sX = smu;                  // 128 x SX2P (tf32 bits)
    uint32_t* sW = smu + 128 * SX2P;     // 128 x SW2P (tf32 bits)
    int tid  = threadIdx.x;
    int row0 = blockIdx.x * 128;

    // load W2 [128 x 40], convert to tf32 once
#pragma unroll
    for (int i = 0; i < 5; i++) {
        int f = tid + i * 256;           // [0, 1280)
        int kr = f / 10, c4 = f - kr * 10;
        float4 v = ((const float4*)W)[(size_t)kr * 10 + c4];
        *((uint4*)(sW + kr * SW2P + c4 * 4)) = f2tf4(v);
    }
    // fused load: x1c = relu(agg1*dinv + b1) + x  -> tf32
#pragma unroll
    for (int i = 0; i < 16; i++) {
        int f = tid + i * 256;          // [0, 4096)
        int r = f >> 5, c4 = f & 31;
        int row = row0 + r;
        float4 o = make_float4(0.f, 0.f, 0.f, 0.f);
        if (row < N) {
            float dv  = g_dinv[row];
            float4 a  = ((const float4*)g_agg1)[(size_t)row * 32 + c4];
            float4 xv = x[(size_t)row * 32 + c4];
            float4 b  = ((const float4*)b1)[c4];
            o.x = fmaxf(fmaf(a.x, dv, b.x), 0.f) + xv.x;
            o.y = fmaxf(fmaf(a.y, dv, b.y), 0.f) + xv.y;
            o.z = fmaxf(fmaf(a.z, dv, b.z), 0.f) + xv.z;
            o.w = fmaxf(fmaf(a.w, dv, b.w), 0.f) + xv.w;
        }
        *((uint4*)(sX + r * SX2P + c4 * 4)) = f2tf4(o);
    }
    __syncthreads();

    int warp = tid >> 5;        // 0..7, each owns 16 rows
    int lane = tid & 31;
    int g   = lane >> 2;        // 0..7
    int tig = lane & 3;         // 0..3

    float acc[5][4];
#pragma unroll
    for (int ni = 0; ni < 5; ni++)
#pragma unroll
        for (int c = 0; c < 4; c++) acc[ni][c] = 0.f;

#pragma unroll
    for (int k0 = 0; k0 < 128; k0 += 8) {
        int r = warp * 16 + g;
        uint32_t a0 = sX[(r)     * SX2P + k0 + tig];
        uint32_t a1 = sX[(r + 8) * SX2P + k0 + tig];
        uint32_t a2 = sX[(r)     * SX2P + k0 + 4 + tig];
        uint32_t a3 = sX[(r + 8) * SX2P + k0 + 4 + tig];
        uint32_t b[5][2];
#pragma unroll
        for (int ni = 0; ni < 5; ni++) {
            int col = ni * 8 + g;
            b[ni][0] = sW[(k0 + tig)     * SW2P + col];
            b[ni][1] = sW[(k0 + 4 + tig) * SW2P + col];
        }
#pragma unroll
        for (int ni = 0; ni < 5; ni++)
            asm volatile(
                "mma.sync.aligned.m16n8k8.row.col.f32.tf32.tf32.f32 "
                "{%0,%1,%2,%3},{%4,%5,%6,%7},{%8,%9},{%0,%1,%2,%3};"
                : "+f"(acc[ni][0]), "+f"(acc[ni][1]),
                  "+f"(acc[ni][2]), "+f"(acc[ni][3])
                : "r"(a0), "r"(a1), "r"(a2), "r"(a3),
                  "r"(b[ni][0]), "r"(b[ni][1]));
    }

    // epilogue: msgs g2h = fp16(acc*dinv); d_out init = acc*dinv^2 + b2
    {
        int r0 = row0 + warp * 16 + g;
        int r1 = r0 + 8;
        float dv0 = (r0 < N) ? g_dinv[r0] : 0.f;
        float dv1 = (r1 < N) ? g_dinv[r1] : 0.f;
#pragma unroll
        for (int ni = 0; ni < 5; ni++) {
            int col = ni * 8 + 2 * tig;
            float2 bb = *((const float2*)(b2 + col));
            if (r0 < N) {
                float2 m = make_float2(acc[ni][0] * dv0, acc[ni][1] * dv0);
                *((__half2*)(g_g2h + (size_t)r0 * 40 + col)) = __float22half2_rn(m);
                float2 o = make_float2(fmaf(m.x, dv0, bb.x), fmaf(m.y, dv0, bb.y));
                *((float2*)(out + (size_t)r0 * 40 + col)) = o;
            }
            if (r1 < N) {
                float2 m = make_float2(acc[ni][2] * dv1, acc[ni][3] * dv1);
                *((__half2*)(g_g2h + (size_t)r1 * 40 + col)) = __float22half2_rn(m);
                float2 o = make_float2(fmaf(m.x, dv1, bb.x), fmaf(m.y, dv1, bb.y));
                *((float2*)(out + (size_t)r1 * 40 + col)) = o;
            }
        }
    }
}

// ------- edge scatter layer 2: out[dst] += fp32(g2h[src]) * dinv[dst] -------
__global__ void scatter2_kernel(float* __restrict__ out, int E) {
    int idx = blockIdx.x * blockDim.x + threadIdx.x;
    if (idx >= E * 10) return;
    int e = idx / 10, c = idx - e * 10;
    int s = g_src[e];
    int d = g_dst[e];
    float dv = g_dinv[d];
    uint2 raw = *((const uint2*)(g_g2h + (size_t)s * 40 + c * 4));
    float2 f0 = __half22float2(*reinterpret_cast<__half2*>(&raw.x));
    float2 f1 = __half22float2(*reinterpret_cast<__half2*>(&raw.y));
    red_add_v4(out + (size_t)d * CDIM + c * 4,
               make_float4(f0.x * dv, f0.y * dv, f1.x * dv, f1.y * dv));
}

extern "C" void kernel_launch(void* const* d_in, const int* in_sizes, int n_in,
                              void* d_out, int out_size) {
    const float* x  = (const float*)d_in[0];
    const void*  ei = (const void*)d_in[1];
    const float* W1 = (const float*)d_in[2];
    const float* b1 = (const float*)d_in[3];
    const float* W2 = (const float*)d_in[4];
    const float* b2 = (const float*)d_in[5];

    int N = in_sizes[0] / FDIM;     // 50000
    int E = in_sizes[1] / 2;        // 800000

    void* degp = nullptr;
    cudaGetSymbolAddress(&degp, g_deg);
    cudaMemsetAsync(degp, 0, (size_t)N * sizeof(int));

    int smem1 = (128 * SXP + 64 * SWP) * sizeof(float);        // ~68 KB
    int smem2 = (128 * SX2P + 128 * SW2P) * sizeof(float);     // ~88 KB
    cudaFuncSetAttribute(gemm1_kernel, cudaFuncAttributeMaxDynamicSharedMemorySize, smem1);
    cudaFuncSetAttribute(gemm2_kernel, cudaFuncAttributeMaxDynamicSharedMemorySize, smem2);

    detect_kernel<<<1, 32>>>((const int*)ei);
    convert_kernel<<<((E + 1) / 2 + 255) / 256, 256>>>(ei, E);
    dinv_kernel<<<(N + 255) / 256, 256>>>(N);

    gemm1_kernel<<<(N + 127) / 128, 256, smem1>>>(x, W1, N);
    {   // 2 edges per warp
        int warps = (E + 1) / 2;
        scatter1_kernel<<<(warps + 7) / 8, 256>>>(E);
    }

    gemm2_kernel<<<(N + 127) / 128, 256, smem2>>>(W2, (const float4*)x, b1, b2,
                                                  (float*)d_out, N);
    scatter2_kernel<<<(E * 10 + 255) / 256, 256>>>((float*)d_out, E);
}

// round 14
// speedup vs baseline: 1.1214x; 1.1214x over previous
#include <cuda_runtime.h>
#include <cuda_fp16.h>
#include <cstdint>

// Problem constants (RestGCNEqualHidden): N=50000, F=H=128, C=40, E=800000
#define MAXN 50016
#define MAXE 800000
#define FDIM 128
#define CDIM 40

// Scratch (device globals -- no allocation allowed)
__device__ int   g_is64;
__device__ int   g_src [MAXE];
__device__ int   g_dst [MAXE];
__device__ int   g_deg [MAXN];
__device__ float g_dinv[MAXN];
__device__ __align__(16) __half g_g1h[(size_t)MAXN * FDIM];  // fp16 msgs L1
__device__ __align__(16) float  g_agg1[(size_t)MAXN * FDIM]; // fp32 accum
__device__ __align__(16) __half g_g2h[(size_t)MAXN * CDIM];  // fp16 msgs L2
__device__ __align__(16) float  g_agg2[(size_t)MAXN * CDIM]; // fp32 accum

__device__ __forceinline__ void red_add_v4(float* addr, float4 v) {
    asm volatile("red.global.add.v4.f32 [%0], {%1,%2,%3,%4};"
                 :: "l"(addr), "f"(v.x), "f"(v.y), "f"(v.z), "f"(v.w)
                 : "memory");
}

__device__ __forceinline__ uint32_t f2tf(float f) {
    uint32_t u;
    asm("cvt.rna.tf32.f32 %0, %1;" : "=r"(u) : "f"(f));
    return u;
}
__device__ __forceinline__ uint4 f2tf4(float4 v) {
    uint4 o;
    o.x = f2tf(v.x); o.y = f2tf(v.y); o.z = f2tf(v.z); o.w = f2tf(v.w);
    return o;
}

// ------- dtype detect (PARALLEL): int64 edges have zero high words ----------
// 128 threads each probe one odd word; ballot-reduce. ~2 loads of latency
// instead of a 128-deep serial load/branch chain.
__global__ void detect_kernel(const int* __restrict__ ei32) {
    __shared__ int s[4];
    int t = threadIdx.x;                       // 0..127
    int bad = (ei32[2 * t + 1] != 0) ? 1 : 0;  // nonzero high word -> int32 data
    unsigned m = __ballot_sync(0xffffffff, bad);
    if ((t & 31) == 0) s[t >> 5] = (m != 0);
    __syncthreads();
    if (t == 0) g_is64 = !(s[0] | s[1] | s[2] | s[3]);
}

// ---------------- convert edges to int32 + degree histogram -----------------
__global__ void convert_kernel(const void* __restrict__ ei, int E) {
    int i = blockIdx.x * blockDim.x + threadIdx.x;
    if (i >= E) return;
    int s, d;
    if (g_is64) {
        const long long* p = (const long long*)ei;
        s = (int)p[i];
        d = (int)p[(size_t)E + i];
    } else {
        const int* p = (const int*)ei;
        s = p[i];
        d = p[E + i];
    }
    g_src[i] = s;
    g_dst[i] = d;
    atomicAdd(&g_deg[d], 1);
}

__global__ void dinv_kernel(int N) {
    int i = blockIdx.x * blockDim.x + threadIdx.x;
    if (i < N) g_dinv[i] = rsqrtf((float)g_deg[i] + 1.0f);  // +1 self loop
}

// ------- GEMM1 (tf32 mma.sync): agg1 = (x @ W1)*dinv ; g1h = fp16(same) -----
// smem holds PRE-CONVERTED tf32 (uint32) -> mainloop is pure LDS + MMA.
// 256 threads = 8 warps (2x4), block tile 128x128, K split in 2 chunks of 64.
#define SXP 68     // sX row stride (pad 4)
#define SWP 136    // sW row stride (pad 8 -> conflict-free B lds)
__global__ __launch_bounds__(256, 2)
void gemm1_kernel(const float* __restrict__ x,
                  const float* __restrict__ W, int N) {
    extern __shared__ uint32_t smu[];
    uint32_t* sX = smu;                 // 128 x SXP  (tf32 bits)
    uint32_t* sW = smu + 128 * SXP;     // 64 x SWP   (tf32 bits)
    int tid  = threadIdx.x;
    int row0 = blockIdx.x * 128;

    int warp  = tid >> 5;
    int lane  = tid & 31;
    int warpM = warp >> 2;           // 0..1  (64 rows each)
    int warpN = warp & 3;            // 0..3  (32 cols each)
    int g   = lane >> 2;             // 0..7
    int tig = lane & 3;              // 0..3

    float acc[4][4][4];
#pragma unroll
    for (int mi = 0; mi < 4; mi++)
#pragma unroll
        for (int ni = 0; ni < 4; ni++)
#pragma unroll
            for (int c = 0; c < 4; c++) acc[mi][ni][c] = 0.f;

    for (int chunk = 0; chunk < 2; chunk++) {
        int kbase = chunk * 64;
        // load W rows [kbase, kbase+64) x 128 cols, convert to tf32 once
#pragma unroll
        for (int i = 0; i < 8; i++) {
            int f = tid + i * 256;          // [0, 2048)
            int kr = f >> 5, c4 = f & 31;
            float4 v = ((const float4*)W)[(size_t)(kbase + kr) * 32 + c4];
            *((uint4*)(sW + kr * SWP + c4 * 4)) = f2tf4(v);
        }
        // load x rows x cols [kbase, kbase+64), convert to tf32 once
#pragma unroll
        for (int i = 0; i < 8; i++) {
            int f = tid + i * 256;          // [0, 2048)
            int r = f >> 4, c4 = f & 15;    // 16 float4 per row
            float4 v = make_float4(0.f, 0.f, 0.f, 0.f);
            if (row0 + r < N)
                v = ((const float4*)x)[(size_t)(row0 + r) * 32 + (kbase >> 2) + c4];
            *((uint4*)(sX + r * SXP + c4 * 4)) = f2tf4(v);
        }
        __syncthreads();

#pragma unroll
        for (int k0 = 0; k0 < 64; k0 += 8) {
            uint32_t a[4][4];
#pragma unroll
            for (int mi = 0; mi < 4; mi++) {
                int r = warpM * 64 + mi * 16 + g;
                a[mi][0] = sX[(r)     * SXP + k0 + tig];
                a[mi][1] = sX[(r + 8) * SXP + k0 + tig];
                a[mi][2] = sX[(r)     * SXP + k0 + 4 + tig];
                a[mi][3] = sX[(r + 8) * SXP + k0 + 4 + tig];
            }
            uint32_t b[4][2];
#pragma unroll
            for (int ni = 0; ni < 4; ni++) {
                int col = warpN * 32 + ni * 8 + g;
                b[ni][0] = sW[(k0 + tig)     * SWP + col];
                b[ni][1] = sW[(k0 + 4 + tig) * SWP + col];
            }
#pragma unroll
            for (int mi = 0; mi < 4; mi++)
#pragma unroll
                for (int ni = 0; ni < 4; ni++)
                    asm volatile(
                        "mma.sync.aligned.m16n8k8.row.col.f32.tf32.tf32.f32 "
                        "{%0,%1,%2,%3},{%4,%5,%6,%7},{%8,%9},{%0,%1,%2,%3};"
                        : "+f"(acc[mi][ni][0]), "+f"(acc[mi][ni][1]),
                          "+f"(acc[mi][ni][2]), "+f"(acc[mi][ni][3])
                        : "r"(a[mi][0]), "r"(a[mi][1]), "r"(a[mi][2]), "r"(a[mi][3]),
                          "r"(b[ni][0]), "r"(b[ni][1]));
        }
        __syncthreads();
    }

    // epilogue: scale by dinv[row]; fp32 -> agg1 (self loop), fp16 -> g1h
#pragma unroll
    for (int mi = 0; mi < 4; mi++) {
        int r0 = row0 + warpM * 64 + mi * 16 + g;
        int r1 = r0 + 8;
        float dv0 = (r0 < N) ? g_dinv[r0] : 0.f;
        float dv1 = (r1 < N) ? g_dinv[r1] : 0.f;
#pragma unroll
        for (int ni = 0; ni < 4; ni++) {
            int col = warpN * 32 + ni * 8 + 2 * tig;
            if (r0 < N) {
                float2 o = make_float2(acc[mi][ni][0] * dv0, acc[mi][ni][1] * dv0);
                *((float2*)(g_agg1 + (size_t)r0 * 128 + col)) = o;
                *((__half2*)(g_g1h + (size_t)r0 * 128 + col)) = __float22half2_rn(o);
            }
            if (r1 < N) {
                float2 o = make_float2(acc[mi][ni][2] * dv1, acc[mi][ni][3] * dv1);
                *((float2*)(g_agg1 + (size_t)r1 * 128 + col)) = o;
                *((__half2*)(g_g1h + (size_t)r1 * 128 + col)) = __float22half2_rn(o);
            }
        }
    }
}

// ------- edge scatter layer 1: agg1[dst] += fp32(g1h[src]) ------------------
__global__ void scatter1_kernel(int E) {
    int w = blockIdx.x * 8 + (threadIdx.x >> 5);
    int lane = threadIdx.x & 31;
    if (w >= E) return;
    int s = g_src[w];
    int d = g_dst[w];
    uint2 raw = *((const uint2*)(g_g1h + (size_t)s * 128 + lane * 4));
    __half2 h0 = *reinterpret_cast<__half2*>(&raw.x);
    __half2 h1 = *reinterpret_cast<__half2*>(&raw.y);
    float2 f0 = __half22float2(h0);
    float2 f1 = __half22float2(h1);
    red_add_v4(&g_agg1[(size_t)d * FDIM + lane * 4],
               make_float4(f0.x, f0.y, f1.x, f1.y));
}

// ---- GEMM2 (tf32 mma) with fused layer-1 epilogue in the load stage --------
// x1c = relu(agg1*dinv + b1) + x computed on the fly -> tf32 into smem, then
// conv2 pre-msgs: agg2 = (x1c @ W2)*dinv fp32, g2h = fp16(same).
#define SX2P 132   // sX row stride
#define SW2P 44    // sW row stride
__global__ __launch_bounds__(256, 2)
void gemm2_kernel(const float* __restrict__ W,
                  const float4* __restrict__ x,
                  const float* __restrict__ b1, int N) {
    extern __shared__ uint32_t smu[];
    uint32_t* sX = smu;                  // 128 x SX2P (tf32 bits)
    uint32_t* sW = smu + 128 * SX2P;     // 128 x SW2P (tf32 bits)
    int tid  = threadIdx.x;
    int row0 = blockIdx.x * 128;

    // load W2 [128 x 40], convert to tf32 once
#pragma unroll
    for (int i = 0; i < 5; i++) {
        int f = tid + i * 256;           // [0, 1280)
        int kr = f / 10, c4 = f - kr * 10;
        float4 v = ((const float4*)W)[(size_t)kr * 10 + c4];
        *((uint4*)(sW + kr * SW2P + c4 * 4)) = f2tf4(v);
    }
    // fused load: x1c = relu(agg1*dinv + b1) + x  -> tf32
#pragma unroll
    for (int i = 0; i < 16; i++) {
        int f = tid + i * 256;          // [0, 4096)
        int r = f >> 5, c4 = f & 31;
        int row = row0 + r;
        float4 o = make_float4(0.f, 0.f, 0.f, 0.f);
        if (row < N) {
            float dv  = g_dinv[row];
            float4 a  = ((const float4*)g_agg1)[(size_t)row * 32 + c4];
            float4 xv = x[(size_t)row * 32 + c4];
            float4 b  = ((const float4*)b1)[c4];
            o.x = fmaxf(fmaf(a.x, dv, b.x), 0.f) + xv.x;
            o.y = fmaxf(fmaf(a.y, dv, b.y), 0.f) + xv.y;
            o.z = fmaxf(fmaf(a.z, dv, b.z), 0.f) + xv.z;
            o.w = fmaxf(fmaf(a.w, dv, b.w), 0.f) + xv.w;
        }
        *((uint4*)(sX + r * SX2P + c4 * 4)) = f2tf4(o);
    }
    __syncthreads();

    int warp = tid >> 5;        // 0..7, each owns 16 rows
    int lane = tid & 31;
    int g   = lane >> 2;        // 0..7
    int tig = lane & 3;         // 0..3

    float acc[5][4];
#pragma unroll
    for (int ni = 0; ni < 5; ni++)
#pragma unroll
        for (int c = 0; c < 4; c++) acc[ni][c] = 0.f;

#pragma unroll
    for (int k0 = 0; k0 < 128; k0 += 8) {
        int r = warp * 16 + g;
        uint32_t a0 = sX[(r)     * SX2P + k0 + tig];
        uint32_t a1 = sX[(r + 8) * SX2P + k0 + tig];
        uint32_t a2 = sX[(r)     * SX2P + k0 + 4 + tig];
        uint32_t a3 = sX[(r + 8) * SX2P + k0 + 4 + tig];
        uint32_t b[5][2];
#pragma unroll
        for (int ni = 0; ni < 5; ni++) {
            int col = ni * 8 + g;
            b[ni][0] = sW[(k0 + tig)     * SW2P + col];
            b[ni][1] = sW[(k0 + 4 + tig) * SW2P + col];
        }
#pragma unroll
        for (int ni = 0; ni < 5; ni++)
            asm volatile(
                "mma.sync.aligned.m16n8k8.row.col.f32.tf32.tf32.f32 "
                "{%0,%1,%2,%3},{%4,%5,%6,%7},{%8,%9},{%0,%1,%2,%3};"
                : "+f"(acc[ni][0]), "+f"(acc[ni][1]),
                  "+f"(acc[ni][2]), "+f"(acc[ni][3])
                : "r"(a0), "r"(a1), "r"(a2), "r"(a3),
                  "r"(b[ni][0]), "r"(b[ni][1]));
    }

    // epilogue: scale by dinv[row]; fp32 -> agg2 (self loop), fp16 -> g2h
    {
        int r0 = row0 + warp * 16 + g;
        int r1 = r0 + 8;
        float dv0 = (r0 < N) ? g_dinv[r0] : 0.f;
        float dv1 = (r1 < N) ? g_dinv[r1] : 0.f;
#pragma unroll
        for (int ni = 0; ni < 5; ni++) {
            int col = ni * 8 + 2 * tig;
            if (r0 < N) {
                float2 o = make_float2(acc[ni][0] * dv0, acc[ni][1] * dv0);
                *((float2*)(g_agg2 + (size_t)r0 * 40 + col)) = o;
                *((__half2*)(g_g2h + (size_t)r0 * 40 + col)) = __float22half2_rn(o);
            }
            if (r1 < N) {
                float2 o = make_float2(acc[ni][2] * dv1, acc[ni][3] * dv1);
                *((float2*)(g_agg2 + (size_t)r1 * 40 + col)) = o;
                *((__half2*)(g_g2h + (size_t)r1 * 40 + col)) = __float22half2_rn(o);
            }
        }
    }
}

// ------- edge scatter layer 2: agg2[dst] += fp32(g2h[src]) ------------------
__global__ void scatter2_kernel(int E) {
    int idx = blockIdx.x * blockDim.x + threadIdx.x;
    if (idx >= E * 10) return;
    int e = idx / 10, c = idx - e * 10;
    int s = g_src[e];
    int d = g_dst[e];
    uint2 raw = *((const uint2*)(g_g2h + (size_t)s * 40 + c * 4));
    __half2 h0 = *reinterpret_cast<__half2*>(&raw.x);
    __half2 h1 = *reinterpret_cast<__half2*>(&raw.y);
    float2 f0 = __half22float2(h0);
    float2 f1 = __half22float2(h1);
    red_add_v4(&g_agg2[(size_t)d * CDIM + c * 4],
               make_float4(f0.x, f0.y, f1.x, f1.y));
}

// ---------------- final: y = agg2 * dinv + b2 ----------------
__global__ void final_kernel(const float* __restrict__ b2,
                             float4* __restrict__ out, int N) {
    int idx = blockIdx.x * blockDim.x + threadIdx.x;
    if (idx >= N * 10) return;
    int r = idx / 10, c = idx - r * 10;
    float dv = g_dinv[r];
    float4 a = ((const float4*)g_agg2)[idx];
    float4 b = ((const float4*)b2)[c];
    float4 o;
    o.x = fmaf(a.x, dv, b.x);
    o.y = fmaf(a.y, dv, b.y);
    o.z = fmaf(a.z, dv, b.z);
    o.w = fmaf(a.w, dv, b.w);
    out[idx] = o;
}

extern "C" void kernel_launch(void* const* d_in, const int* in_sizes, int n_in,
                              void* d_out, int out_size) {
    const float* x  = (const float*)d_in[0];
    const void*  ei = (const void*)d_in[1];
    const float* W1 = (const float*)d_in[2];
    const float* b1 = (const float*)d_in[3];
    const float* W2 = (const float*)d_in[4];
    const float* b2 = (const float*)d_in[5];

    int N = in_sizes[0] / FDIM;     // 50000
    int E = in_sizes[1] / 2;        // 800000

    void* degp = nullptr;
    cudaGetSymbolAddress(&degp, g_deg);
    cudaMemsetAsync(degp, 0, (size_t)N * sizeof(int));

    int smem1 = (128 * SXP + 64 * SWP) * sizeof(float);        // ~68 KB
    int smem2 = (128 * SX2P + 128 * SW2P) * sizeof(float);     // ~88 KB
    cudaFuncSetAttribute(gemm1_kernel, cudaFuncAttributeMaxDynamicSharedMemorySize, smem1);
    cudaFuncSetAttribute(gemm2_kernel, cudaFuncAttributeMaxDynamicSharedMemorySize, smem2);

    detect_kernel<<<1, 128>>>((const int*)ei);
    convert_kernel<<<(E + 255) / 256, 256>>>(ei, E);
    dinv_kernel<<<(N + 255) / 256, 256>>>(N);

    gemm1_kernel<<<(N + 127) / 128, 256, smem1>>>(x, W1, N);
    scatter1_kernel<<<(E + 7) / 8, 256>>>(E);

    gemm2_kernel<<<(N + 127) / 128, 256, smem2>>>(W2, (const float4*)x, b1, N);
    scatter2_kernel<<<(E * 10 + 255) / 256, 256>>>(E);
    final_kernel<<<(N * 10 + 255) / 256, 256>>>(b2, (float4*)d_out, N);
}

// round 15
// speedup vs baseline: 1.1263x; 1.0043x over previous
#include <cuda_runtime.h>
#include <cuda_fp16.h>
#include <cstdint>

// Problem constants (RestGCNEqualHidden): N=50000, F=H=128, C=40, E=800000
#define MAXN 50016
#define MAXE 800000
#define FDIM 128
#define CDIM 40

// Scratch (device globals -- no allocation allowed)
__device__ int   g_is64;
__device__ int   g_src [MAXE];
__device__ int   g_dst [MAXE];
__device__ int   g_deg [MAXN];
__device__ float g_dinv[MAXN];
__device__ __align__(16) __half g_g1h[(size_t)MAXN * FDIM];  // fp16 msgs L1
__device__ __align__(16) float  g_agg1[(size_t)MAXN * FDIM]; // fp32 accum
__device__ __align__(16) __half g_g2h[(size_t)MAXN * CDIM];  // fp16 msgs L2

__device__ __forceinline__ void red_add_v4(float* addr, float4 v) {
    asm volatile("red.global.add.v4.f32 [%0], {%1,%2,%3,%4};"
                 :: "l"(addr), "f"(v.x), "f"(v.y), "f"(v.z), "f"(v.w)
                 : "memory");
}

__device__ __forceinline__ uint32_t f2tf(float f) {
    uint32_t u;
    asm("cvt.rna.tf32.f32 %0, %1;" : "=r"(u) : "f"(f));
    return u;
}
__device__ __forceinline__ uint4 f2tf4(float4 v) {
    uint4 o;
    o.x = f2tf(v.x); o.y = f2tf(v.y); o.z = f2tf(v.z); o.w = f2tf(v.w);
    return o;
}

// ------- dtype detect (PARALLEL): int64 edges have zero high words ----------
__global__ void detect_kernel(const int* __restrict__ ei32) {
    __shared__ int s[4];
    int t = threadIdx.x;                       // 0..127
    int bad = (ei32[2 * t + 1] != 0) ? 1 : 0;  // nonzero high word -> int32 data
    unsigned m = __ballot_sync(0xffffffff, bad);
    if ((t & 31) == 0) s[t >> 5] = (m != 0);
    __syncthreads();
    if (t == 0) g_is64 = !(s[0] | s[1] | s[2] | s[3]);
}

// ---------------- convert edges to int32 + degree histogram -----------------
__global__ void convert_kernel(const void* __restrict__ ei, int E) {
    int i = blockIdx.x * blockDim.x + threadIdx.x;
    if (i >= E) return;
    int s, d;
    if (g_is64) {
        const long long* p = (const long long*)ei;
        s = (int)p[i];
        d = (int)p[(size_t)E + i];
    } else {
        const int* p = (const int*)ei;
        s = p[i];
        d = p[E + i];
    }
    g_src[i] = s;
    g_dst[i] = d;
    atomicAdd(&g_deg[d], 1);
}

__global__ void dinv_kernel(int N) {
    int i = blockIdx.x * blockDim.x + threadIdx.x;
    if (i < N) g_dinv[i] = rsqrtf((float)g_deg[i] + 1.0f);  // +1 self loop
}

// ------- GEMM1 (tf32 mma.sync): agg1 = (x @ W1)*dinv ; g1h = fp16(same) -----
// smem holds PRE-CONVERTED tf32 (uint32) -> mainloop is pure LDS + MMA.
// 256 threads = 8 warps (2x4), block tile 128x128, K split in 2 chunks of 64.
#define SXP 68     // sX row stride (pad 4)
#define SWP 136    // sW row stride (pad 8 -> conflict-free B lds)
__global__ __launch_bounds__(256, 2)
void gemm1_kernel(const float* __restrict__ x,
                  const float* __restrict__ W, int N) {
    extern __shared__ uint32_t smu[];
    uint32_t* sX = smu;                 // 128 x SXP  (tf32 bits)
    uint32_t* sW = smu + 128 * SXP;     // 64 x SWP   (tf32 bits)
    int tid  = threadIdx.x;
    int row0 = blockIdx.x * 128;

    int warp  = tid >> 5;
    int lane  = tid & 31;
    int warpM = warp >> 2;           // 0..1  (64 rows each)
    int warpN = warp & 3;            // 0..3  (32 cols each)
    int g   = lane >> 2;             // 0..7
    int tig = lane & 3;              // 0..3

    float acc[4][4][4];
#pragma unroll
    for (int mi = 0; mi < 4; mi++)
#pragma unroll
        for (int ni = 0; ni < 4; ni++)
#pragma unroll
            for (int c = 0; c < 4; c++) acc[mi][ni][c] = 0.f;

    for (int chunk = 0; chunk < 2; chunk++) {
        int kbase = chunk * 64;
        // load W rows [kbase, kbase+64) x 128 cols, convert to tf32 once
#pragma unroll
        for (int i = 0; i < 8; i++) {
            int f = tid + i * 256;          // [0, 2048)
            int kr = f >> 5, c4 = f & 31;
            float4 v = ((const float4*)W)[(size_t)(kbase + kr) * 32 + c4];
            *((uint4*)(sW + kr * SWP + c4 * 4)) = f2tf4(v);
        }
        // load x rows x cols [kbase, kbase+64), convert to tf32 once
#pragma unroll
        for (int i = 0; i < 8; i++) {
            int f = tid + i * 256;          // [0, 2048)
            int r = f >> 4, c4 = f & 15;    // 16 float4 per row
            float4 v = make_float4(0.f, 0.f, 0.f, 0.f);
            if (row0 + r < N)
                v = ((const float4*)x)[(size_t)(row0 + r) * 32 + (kbase >> 2) + c4];
            *((uint4*)(sX + r * SXP + c4 * 4)) = f2tf4(v);
        }
        __syncthreads();

#pragma unroll
        for (int k0 = 0; k0 < 64; k0 += 8) {
            uint32_t a[4][4];
#pragma unroll
            for (int mi = 0; mi < 4; mi++) {
                int r = warpM * 64 + mi * 16 + g;
                a[mi][0] = sX[(r)     * SXP + k0 + tig];
                a[mi][1] = sX[(r + 8) * SXP + k0 + tig];
                a[mi][2] = sX[(r)     * SXP + k0 + 4 + tig];
                a[mi][3] = sX[(r + 8) * SXP + k0 + 4 + tig];
            }
            uint32_t b[4][2];
#pragma unroll
            for (int ni = 0; ni < 4; ni++) {
                int col = warpN * 32 + ni * 8 + g;
                b[ni][0] = sW[(k0 + tig)     * SWP + col];
                b[ni][1] = sW[(k0 + 4 + tig) * SWP + col];
            }
#pragma unroll
            for (int mi = 0; mi < 4; mi++)
#pragma unroll
                for (int ni = 0; ni < 4; ni++)
                    asm volatile(
                        "mma.sync.aligned.m16n8k8.row.col.f32.tf32.tf32.f32 "
                        "{%0,%1,%2,%3},{%4,%5,%6,%7},{%8,%9},{%0,%1,%2,%3};"
                        : "+f"(acc[mi][ni][0]), "+f"(acc[mi][ni][1]),
                          "+f"(acc[mi][ni][2]), "+f"(acc[mi][ni][3])
                        : "r"(a[mi][0]), "r"(a[mi][1]), "r"(a[mi][2]), "r"(a[mi][3]),
                          "r"(b[ni][0]), "r"(b[ni][1]));
        }
        __syncthreads();
    }

    // epilogue: scale by dinv[row]; fp32 -> agg1 (self loop), fp16 -> g1h
#pragma unroll
    for (int mi = 0; mi < 4; mi++) {
        int r0 = row0 + warpM * 64 + mi * 16 + g;
        int r1 = r0 + 8;
        float dv0 = (r0 < N) ? g_dinv[r0] : 0.f;
        float dv1 = (r1 < N) ? g_dinv[r1] : 0.f;
#pragma unroll
        for (int ni = 0; ni < 4; ni++) {
            int col = warpN * 32 + ni * 8 + 2 * tig;
            if (r0 < N) {
                float2 o = make_float2(acc[mi][ni][0] * dv0, acc[mi][ni][1] * dv0);
                *((float2*)(g_agg1 + (size_t)r0 * 128 + col)) = o;
                *((__half2*)(g_g1h + (size_t)r0 * 128 + col)) = __float22half2_rn(o);
            }
            if (r1 < N) {
                float2 o = make_float2(acc[mi][ni][2] * dv1, acc[mi][ni][3] * dv1);
                *((float2*)(g_agg1 + (size_t)r1 * 128 + col)) = o;
                *((__half2*)(g_g1h + (size_t)r1 * 128 + col)) = __float22half2_rn(o);
            }
        }
    }
}

// ------- edge scatter layer 1: agg1[dst] += fp32(g1h[src]) ------------------
__global__ void scatter1_kernel(int E) {
    int w = blockIdx.x * 8 + (threadIdx.x >> 5);
    int lane = threadIdx.x & 31;
    if (w >= E) return;
    int s = g_src[w];
    int d = g_dst[w];
    uint2 raw = *((const uint2*)(g_g1h + (size_t)s * 128 + lane * 4));
    __half2 h0 = *reinterpret_cast<__half2*>(&raw.x);
    __half2 h1 = *reinterpret_cast<__half2*>(&raw.y);
    float2 f0 = __half22float2(h0);
    float2 f1 = __half22float2(h1);
    red_add_v4(&g_agg1[(size_t)d * FDIM + lane * 4],
               make_float4(f0.x, f0.y, f1.x, f1.y));
}

// ---- GEMM2 (tf32 mma) with fused layer-1 epilogue in the load stage --------
// x1c = relu(agg1*dinv + b1) + x computed on the fly -> tf32 into smem, then
// self-loop of conv2 goes STRAIGHT to d_out: out = acc*dinv^2 + b2;
// fp16 pre-scaled messages g2h = fp16(acc*dinv) for scatter2.
#define SX2P 132   // sX row stride
#define SW2P 44    // sW row stride
__global__ __launch_bounds__(256, 2)
void gemm2_kernel(const float* __restrict__ W,
                  const float4* __restrict__ x,
                  const float* __restrict__ b1,
                  const float* __restrict__ b2,
                  float* __restrict__ out, int N) {
    extern __shared__ uint32_t smu[];
    uint32_t* sX = smu;                  // 128 x SX2P (tf32 bits)
    uint32_t* sW = smu + 128 * SX2P;     // 128 x SW2P (tf32 bits)
    int tid  = threadIdx.x;
    int row0 = blockIdx.x * 128;

    // load W2 [128 x 40], convert to tf32 once
#pragma unroll
    for (int i = 0; i < 5; i++) {
        int f = tid + i * 256;           // [0, 1280)
        int kr = f / 10, c4 = f - kr * 10;
        float4 v = ((const float4*)W)[(size_t)kr * 10 + c4];
        *((uint4*)(sW + kr * SW2P + c4 * 4)) = f2tf4(v);
    }
    // fused load: x1c = relu(agg1*dinv + b1) + x  -> tf32
#pragma unroll
    for (int i = 0; i < 16; i++) {
        int f = tid + i * 256;          // [0, 4096)
        int r = f >> 5, c4 = f & 31;
        int row = row0 + r;
        float4 o = make_float4(0.f, 0.f, 0.f, 0.f);
        if (row < N) {
            float dv  = g_dinv[row];
            float4 a  = ((const float4*)g_agg1)[(size_t)row * 32 + c4];
            float4 xv = x[(size_t)row * 32 + c4];
            float4 b  = ((const float4*)b1)[c4];
            o.x = fmaxf(fmaf(a.x, dv, b.x), 0.f) + xv.x;
            o.y = fmaxf(fmaf(a.y, dv, b.y), 0.f) + xv.y;
            o.z = fmaxf(fmaf(a.z, dv, b.z), 0.f) + xv.z;
            o.w = fmaxf(fmaf(a.w, dv, b.w), 0.f) + xv.w;
        }
        *((uint4*)(sX + r * SX2P + c4 * 4)) = f2tf4(o);
    }
    __syncthreads();

    int warp = tid >> 5;        // 0..7, each owns 16 rows
    int lane = tid & 31;
    int g   = lane >> 2;        // 0..7
    int tig = lane & 3;         // 0..3

    float acc[5][4];
#pragma unroll
    for (int ni = 0; ni < 5; ni++)
#pragma unroll
        for (int c = 0; c < 4; c++) acc[ni][c] = 0.f;

#pragma unroll
    for (int k0 = 0; k0 < 128; k0 += 8) {
        int r = warp * 16 + g;
        uint32_t a0 = sX[(r)     * SX2P + k0 + tig];
        uint32_t a1 = sX[(r + 8) * SX2P + k0 + tig];
        uint32_t a2 = sX[(r)     * SX2P + k0 + 4 + tig];
        uint32_t a3 = sX[(r + 8) * SX2P + k0 + 4 + tig];
        uint32_t b[5][2];
#pragma unroll
        for (int ni = 0; ni < 5; ni++) {
            int col = ni * 8 + g;
            b[ni][0] = sW[(k0 + tig)     * SW2P + col];
            b[ni][1] = sW[(k0 + 4 + tig) * SW2P + col];
        }
#pragma unroll
        for (int ni = 0; ni < 5; ni++)
            asm volatile(
                "mma.sync.aligned.m16n8k8.row.col.f32.tf32.tf32.f32 "
                "{%0,%1,%2,%3},{%4,%5,%6,%7},{%8,%9},{%0,%1,%2,%3};"
                : "+f"(acc[ni][0]), "+f"(acc[ni][1]),
                  "+f"(acc[ni][2]), "+f"(acc[ni][3])
                : "r"(a0), "r"(a1), "r"(a2), "r"(a3),
                  "r"(b[ni][0]), "r"(b[ni][1]));
    }

    // epilogue: msgs g2h = fp16(acc*dinv); d_out init = acc*dinv^2 + b2
    {
        int r0 = row0 + warp * 16 + g;
        int r1 = r0 + 8;
        float dv0 = (r0 < N) ? g_dinv[r0] : 0.f;
        float dv1 = (r1 < N) ? g_dinv[r1] : 0.f;
#pragma unroll
        for (int ni = 0; ni < 5; ni++) {
            int col = ni * 8 + 2 * tig;
            float2 bb = *((const float2*)(b2 + col));
            if (r0 < N) {
                float2 m = make_float2(acc[ni][0] * dv0, acc[ni][1] * dv0);
                *((__half2*)(g_g2h + (size_t)r0 * 40 + col)) = __float22half2_rn(m);
                float2 o = make_float2(fmaf(m.x, dv0, bb.x), fmaf(m.y, dv0, bb.y));
                *((float2*)(out + (size_t)r0 * 40 + col)) = o;
            }
            if (r1 < N) {
                float2 m = make_float2(acc[ni][2] * dv1, acc[ni][3] * dv1);
                *((__half2*)(g_g2h + (size_t)r1 * 40 + col)) = __float22half2_rn(m);
                float2 o = make_float2(fmaf(m.x, dv1, bb.x), fmaf(m.y, dv1, bb.y));
                *((float2*)(out + (size_t)r1 * 40 + col)) = o;
            }
        }
    }
}

// ------- edge scatter layer 2: out[dst] += fp32(g2h[src]) * dinv[dst] -------
__global__ void scatter2_kernel(float* __restrict__ out, int E) {
    int idx = blockIdx.x * blockDim.x + threadIdx.x;
    if (idx >= E * 10) return;
    int e = idx / 10, c = idx - e * 10;
    int s = g_src[e];
    int d = g_dst[e];
    float dv = g_dinv[d];
    uint2 raw = *((const uint2*)(g_g2h + (size_t)s * 40 + c * 4));
    float2 f0 = __half22float2(*reinterpret_cast<__half2*>(&raw.x));
    float2 f1 = __half22float2(*reinterpret_cast<__half2*>(&raw.y));
    red_add_v4(out + (size_t)d * CDIM + c * 4,
               make_float4(f0.x * dv, f0.y * dv, f1.x * dv, f1.y * dv));
}

extern "C" void kernel_launch(void* const* d_in, const int* in_sizes, int n_in,
                              void* d_out, int out_size) {
    const float* x  = (const float*)d_in[0];
    const void*  ei = (const void*)d_in[1];
    const float* W1 = (const float*)d_in[2];
    const float* b1 = (const float*)d_in[3];
    const float* W2 = (const float*)d_in[4];
    const float* b2 = (const float*)d_in[5];

    int N = in_sizes[0] / FDIM;     // 50000
    int E = in_sizes[1] / 2;        // 800000

    void* degp = nullptr;
    cudaGetSymbolAddress(&degp, g_deg);
    cudaMemsetAsync(degp, 0, (size_t)N * sizeof(int));

    int smem1 = (128 * SXP + 64 * SWP) * sizeof(float);        // ~68 KB
    int smem2 = (128 * SX2P + 128 * SW2P) * sizeof(float);     // ~88 KB
    cudaFuncSetAttribute(gemm1_kernel, cudaFuncAttributeMaxDynamicSharedMemorySize, smem1);
    cudaFuncSetAttribute(gemm2_kernel, cudaFuncAttributeMaxDynamicSharedMemorySize, smem2);

    detect_kernel<<<1, 128>>>((const int*)ei);
    convert_kernel<<<(E + 255) / 256, 256>>>(ei, E);
    dinv_kernel<<<(N + 255) / 256, 256>>>(N);

    gemm1_kernel<<<(N + 127) / 128, 256, smem1>>>(x, W1, N);
    scatter1_kernel<<<(E + 7) / 8, 256>>>(E);

    gemm2_kernel<<<(N + 127) / 128, 256, smem2>>>(W2, (const float4*)x, b1, b2,
                                                  (float*)d_out, N);
    scatter2_kernel<<<(E * 10 + 255) / 256, 256>>>((float*)d_out, E);
}

// round 16
// speedup vs baseline: 1.1797x; 1.0474x over previous
#include <cuda_runtime.h>
#include <cuda_fp16.h>
#include <cstdint>

// Problem constants (RestGCNEqualHidden): N=50000, F=H=128, C=40, E=800000
#define MAXN 50016
#define MAXE 800000
#define FDIM 128
#define CDIM 40

// Scratch (device globals -- no allocation allowed)
__device__ int   g_is64;
__device__ int   g_src [MAXE];
__device__ int   g_dst [MAXE];
__device__ int   g_deg [MAXN];
__device__ float g_dinv[MAXN];
__device__ __align__(16) __half g_g1h[(size_t)MAXN * FDIM];  // fp16 msgs L1
__device__ __align__(16) float  g_agg1[(size_t)MAXN * FDIM]; // fp32 accum
__device__ __align__(16) __half g_g2h[(size_t)MAXN * CDIM];  // fp16 msgs L2

__device__ __forceinline__ void red_add_v4(float* addr, float4 v) {
    asm volatile("red.global.add.v4.f32 [%0], {%1,%2,%3,%4};"
                 :: "l"(addr), "f"(v.x), "f"(v.y), "f"(v.z), "f"(v.w)
                 : "memory");
}

__device__ __forceinline__ uint32_t f2tf(float f) {
    uint32_t u;
    asm("cvt.rna.tf32.f32 %0, %1;" : "=r"(u) : "f"(f));
    return u;
}
__device__ __forceinline__ uint4 f2tf4(float4 v) {
    uint4 o;
    o.x = f2tf(v.x); o.y = f2tf(v.y); o.z = f2tf(v.z); o.w = f2tf(v.w);
    return o;
}

// ldmatrix x4 (b16 form) — for tf32 A-fragments: lane gets word (row=L/4, col=L%4)
__device__ __forceinline__ void ldsm_x4(uint32_t& r0, uint32_t& r1,
                                        uint32_t& r2, uint32_t& r3,
                                        uint32_t smem_addr) {
    asm volatile("ldmatrix.sync.aligned.m8n8.x4.shared.b16 {%0,%1,%2,%3}, [%4];"
                 : "=r"(r0), "=r"(r1), "=r"(r2), "=r"(r3) : "r"(smem_addr));
}

// ------- dtype detect (PARALLEL): int64 edges have zero high words ----------
__global__ void detect_kernel(const int* __restrict__ ei32) {
    __shared__ int s[4];
    int t = threadIdx.x;                       // 0..127
    int bad = (ei32[2 * t + 1] != 0) ? 1 : 0;  // nonzero high word -> int32 data
    unsigned m = __ballot_sync(0xffffffff, bad);
    if ((t & 31) == 0) s[t >> 5] = (m != 0);
    __syncthreads();
    if (t == 0) g_is64 = !(s[0] | s[1] | s[2] | s[3]);
}

// ---------------- convert edges to int32 + degree histogram -----------------
__global__ void convert_kernel(const void* __restrict__ ei, int E) {
    int i = blockIdx.x * blockDim.x + threadIdx.x;
    if (i >= E) return;
    int s, d;
    if (g_is64) {
        const long long* p = (const long long*)ei;
        s = (int)p[i];
        d = (int)p[(size_t)E + i];
    } else {
        const int* p = (const int*)ei;
        s = p[i];
        d = p[E + i];
    }
    g_src[i] = s;
    g_dst[i] = d;
    atomicAdd(&g_deg[d], 1);
}

__global__ void dinv_kernel(int N) {
    int i = blockIdx.x * blockDim.x + threadIdx.x;
    if (i < N) g_dinv[i] = rsqrtf((float)g_deg[i] + 1.0f);  // +1 self loop
}

// ------- GEMM1 (tf32 mma.sync): agg1 = (x @ W1)*dinv ; g1h = fp16(same) -----
// smem holds PRE-CONVERTED tf32; A-fragments fed by ldmatrix.x4 (4 LDSM/k0
// instead of 16 scalar LDS). 256 threads, block tile 128x128, K 2 chunks of 64.
#define SXP 68     // sX row stride (pad 4)
#define SWP 136    // sW row stride (pad 8 -> conflict-free B lds)
__global__ __launch_bounds__(256, 2)
void gemm1_kernel(const float* __restrict__ x,
                  const float* __restrict__ W, int N) {
    extern __shared__ uint32_t smu[];
    uint32_t* sX = smu;                 // 128 x SXP  (tf32 bits)
    uint32_t* sW = smu + 128 * SXP;     // 64 x SWP   (tf32 bits)
    int tid  = threadIdx.x;
    int row0 = blockIdx.x * 128;

    int warp  = tid >> 5;
    int lane  = tid & 31;
    int warpM = warp >> 2;           // 0..1  (64 rows each)
    int warpN = warp & 3;            // 0..3  (32 cols each)
    int g   = lane >> 2;             // 0..7
    int tig = lane & 3;              // 0..3

    // ldmatrix lane-address components: sub 0..3 selects (row+8?, col+4?)
    int sub    = lane >> 3;
    int lrow   = (lane & 7) + ((sub & 1) << 3);   // 0..15
    int lcoloff = (sub & 2) << 1;                 // 0 or 4

    float acc[4][4][4];
#pragma unroll
    for (int mi = 0; mi < 4; mi++)
#pragma unroll
        for (int ni = 0; ni < 4; ni++)
#pragma unroll
            for (int c = 0; c < 4; c++) acc[mi][ni][c] = 0.f;

    for (int chunk = 0; chunk < 2; chunk++) {
        int kbase = chunk * 64;
        // load W rows [kbase, kbase+64) x 128 cols, convert to tf32 once
#pragma unroll
        for (int i = 0; i < 8; i++) {
            int f = tid + i * 256;          // [0, 2048)
            int kr = f >> 5, c4 = f & 31;
            float4 v = ((const float4*)W)[(size_t)(kbase + kr) * 32 + c4];
            *((uint4*)(sW + kr * SWP + c4 * 4)) = f2tf4(v);
        }
        // load x rows x cols [kbase, kbase+64), convert to tf32 once
#pragma unroll
        for (int i = 0; i < 8; i++) {
            int f = tid + i * 256;          // [0, 2048)
            int r = f >> 4, c4 = f & 15;    // 16 float4 per row
            float4 v = make_float4(0.f, 0.f, 0.f, 0.f);
            if (row0 + r < N)
                v = ((const float4*)x)[(size_t)(row0 + r) * 32 + (kbase >> 2) + c4];
            *((uint4*)(sX + r * SXP + c4 * 4)) = f2tf4(v);
        }
        __syncthreads();

#pragma unroll
        for (int k0 = 0; k0 < 64; k0 += 8) {
            uint32_t a[4][4];
#pragma unroll
            for (int mi = 0; mi < 4; mi++) {
                int row = warpM * 64 + mi * 16 + lrow;
                uint32_t addr = (uint32_t)__cvta_generic_to_shared(
                    sX + row * SXP + k0 + lcoloff);
                ldsm_x4(a[mi][0], a[mi][1], a[mi][2], a[mi][3], addr);
            }
            uint32_t b[4][2];
#pragma unroll
            for (int ni = 0; ni < 4; ni++) {
                int col = warpN * 32 + ni * 8 + g;
                b[ni][0] = sW[(k0 + tig)     * SWP + col];
                b[ni][1] = sW[(k0 + 4 + tig) * SWP + col];
            }
#pragma unroll
            for (int mi = 0; mi < 4; mi++)
#pragma unroll
                for (int ni = 0; ni < 4; ni++)
                    asm volatile(
                        "mma.sync.aligned.m16n8k8.row.col.f32.tf32.tf32.f32 "
                        "{%0,%1,%2,%3},{%4,%5,%6,%7},{%8,%9},{%0,%1,%2,%3};"
                        : "+f"(acc[mi][ni][0]), "+f"(acc[mi][ni][1]),
                          "+f"(acc[mi][ni][2]), "+f"(acc[mi][ni][3])
                        : "r"(a[mi][0]), "r"(a[mi][1]), "r"(a[mi][2]), "r"(a[mi][3]),
                          "r"(b[ni][0]), "r"(b[ni][1]));
        }
        __syncthreads();
    }

    // epilogue: scale by dinv[row]; fp32 -> agg1 (self loop), fp16 -> g1h
#pragma unroll
    for (int mi = 0; mi < 4; mi++) {
        int r0 = row0 + warpM * 64 + mi * 16 + g;
        int r1 = r0 + 8;
        float dv0 = (r0 < N) ? g_dinv[r0] : 0.f;
        float dv1 = (r1 < N) ? g_dinv[r1] : 0.f;
#pragma unroll
        for (int ni = 0; ni < 4; ni++) {
            int col = warpN * 32 + ni * 8 + 2 * tig;
            if (r0 < N) {
                float2 o = make_float2(acc[mi][ni][0] * dv0, acc[mi][ni][1] * dv0);
                *((float2*)(g_agg1 + (size_t)r0 * 128 + col)) = o;
                *((__half2*)(g_g1h + (size_t)r0 * 128 + col)) = __float22half2_rn(o);
            }
            if (r1 < N) {
                float2 o = make_float2(acc[mi][ni][2] * dv1, acc[mi][ni][3] * dv1);
                *((float2*)(g_agg1 + (size_t)r1 * 128 + col)) = o;
                *((__half2*)(g_g1h + (size_t)r1 * 128 + col)) = __float22half2_rn(o);
            }
        }
    }
}

// ------- edge scatter layer 1: agg1[dst] += fp32(g1h[src]) ------------------
__global__ void scatter1_kernel(int E) {
    int w = blockIdx.x * 8 + (threadIdx.x >> 5);
    int lane = threadIdx.x & 31;
    if (w >= E) return;
    int s = g_src[w];
    int d = g_dst[w];
    uint2 raw = *((const uint2*)(g_g1h + (size_t)s * 128 + lane * 4));
    __half2 h0 = *reinterpret_cast<__half2*>(&raw.x);
    __half2 h1 = *reinterpret_cast<__half2*>(&raw.y);
    float2 f0 = __half22float2(h0);
    float2 f1 = __half22float2(h1);
    red_add_v4(&g_agg1[(size_t)d * FDIM + lane * 4],
               make_float4(f0.x, f0.y, f1.x, f1.y));
}

// ---- GEMM2 (tf32 mma) with fused layer-1 epilogue in the load stage --------
// x1c = relu(agg1*dinv + b1) + x on the fly -> tf32 smem; A frags via ldmatrix;
// self-loop of conv2 goes straight to d_out; g2h = fp16(acc*dinv) for scatter2.
#define SX2P 132   // sX row stride
#define SW2P 44    // sW row stride
__global__ __launch_bounds__(256, 2)
void gemm2_kernel(const float* __restrict__ W,
                  const float4* __restrict__ x,
                  const float* __restrict__ b1,
                  const float* __restrict__ b2,
                  float* __restrict__ out, int N) {
    extern __shared__ uint32_t smu[];
    uint32_t* sX = smu;                  // 128 x SX2P (tf32 bits)
    uint32_t* sW = smu + 128 * SX2P;     // 128 x SW2P (tf32 bits)
    int tid  = threadIdx.x;
    int row0 = blockIdx.x * 128;

    // load W2 [128 x 40], convert to tf32 once
#pragma unroll
    for (int i = 0; i < 5; i++) {
        int f = tid + i * 256;           // [0, 1280)
        int kr = f / 10, c4 = f - kr * 10;
        float4 v = ((const float4*)W)[(size_t)kr * 10 + c4];
        *((uint4*)(sW + kr * SW2P + c4 * 4)) = f2tf4(v);
    }
    // fused load: x1c = relu(agg1*dinv + b1) + x  -> tf32
#pragma unroll
    for (int i = 0; i < 16; i++) {
        int f = tid + i * 256;          // [0, 4096)
        int r = f >> 5, c4 = f & 31;
        int row = row0 + r;
        float4 o = make_float4(0.f, 0.f, 0.f, 0.f);
        if (row < N) {
            float dv  = g_dinv[row];
            float4 a  = ((const float4*)g_agg1)[(size_t)row * 32 + c4];
            float4 xv = x[(size_t)row * 32 + c4];
            float4 b  = ((const float4*)b1)[c4];
            o.x = fmaxf(fmaf(a.x, dv, b.x), 0.f) + xv.x;
            o.y = fmaxf(fmaf(a.y, dv, b.y), 0.f) + xv.y;
            o.z = fmaxf(fmaf(a.z, dv, b.z), 0.f) + xv.z;
            o.w = fmaxf(fmaf(a.w, dv, b.w), 0.f) + xv.w;
        }
        *((uint4*)(sX + r * SX2P + c4 * 4)) = f2tf4(o);
    }
    __syncthreads();

    int warp = tid >> 5;        // 0..7, each owns 16 rows
    int lane = tid & 31;
    int g   = lane >> 2;        // 0..7
    int tig = lane & 3;         // 0..3

    int sub    = lane >> 3;
    int lrow   = (lane & 7) + ((sub & 1) << 3);   // 0..15
    int lcoloff = (sub & 2) << 1;                 // 0 or 4

    float acc[5][4];
#pragma unroll
    for (int ni = 0; ni < 5; ni++)
#pragma unroll
        for (int c = 0; c < 4; c++) acc[ni][c] = 0.f;

#pragma unroll
    for (int k0 = 0; k0 < 128; k0 += 8) {
        uint32_t a0, a1, a2, a3;
        {
            int row = warp * 16 + lrow;
            uint32_t addr = (uint32_t)__cvta_generic_to_shared(
                sX + row * SX2P + k0 + lcoloff);
            ldsm_x4(a0, a1, a2, a3, addr);
        }
        uint32_t b[5][2];
#pragma unroll
        for (int ni = 0; ni < 5; ni++) {
            int col = ni * 8 + g;
            b[ni][0] = sW[(k0 + tig)     * SW2P + col];
            b[ni][1] = sW[(k0 + 4 + tig) * SW2P + col];
        }
#pragma unroll
        for (int ni = 0; ni < 5; ni++)
            asm volatile(
                "mma.sync.aligned.m16n8k8.row.col.f32.tf32.tf32.f32 "
                "{%0,%1,%2,%3},{%4,%5,%6,%7},{%8,%9},{%0,%1,%2,%3};"
                : "+f"(acc[ni][0]), "+f"(acc[ni][1]),
                  "+f"(acc[ni][2]), "+f"(acc[ni][3])
                : "r"(a0), "r"(a1), "r"(a2), "r"(a3),
                  "r"(b[ni][0]), "r"(b[ni][1]));
    }

    // epilogue: msgs g2h = fp16(acc*dinv); d_out init = acc*dinv^2 + b2
    {
        int r0 = row0 + warp * 16 + g;
        int r1 = r0 + 8;
        float dv0 = (r0 < N) ? g_dinv[r0] : 0.f;
        float dv1 = (r1 < N) ? g_dinv[r1] : 0.f;
#pragma unroll
        for (int ni = 0; ni < 5; ni++) {
            int col = ni * 8 + 2 * tig;
            float2 bb = *((const float2*)(b2 + col));
            if (r0 < N) {
                float2 m = make_float2(acc[ni][0] * dv0, acc[ni][1] * dv0);
                *((__half2*)(g_g2h + (size_t)r0 * 40 + col)) = __float22half2_rn(m);
                float2 o = make_float2(fmaf(m.x, dv0, bb.x), fmaf(m.y, dv0, bb.y));
                *((float2*)(out + (size_t)r0 * 40 + col)) = o;
            }
            if (r1 < N) {
                float2 m = make_float2(acc[ni][2] * dv1, acc[ni][3] * dv1);
                *((__half2*)(g_g2h + (size_t)r1 * 40 + col)) = __float22half2_rn(m);
                float2 o = make_float2(fmaf(m.x, dv1, bb.x), fmaf(m.y, dv1, bb.y));
                *((float2*)(out + (size_t)r1 * 40 + col)) = o;
            }
        }
    }
}

// ------- edge scatter layer 2: out[dst] += fp32(g2h[src]) * dinv[dst] -------
__global__ void scatter2_kernel(float* __restrict__ out, int E) {
    int idx = blockIdx.x * blockDim.x + threadIdx.x;
    if (idx >= E * 10) return;
    int e = idx / 10, c = idx - e * 10;
    int s = g_src[e];
    int d = g_dst[e];
    float dv = g_dinv[d];
    uint2 raw = *((const uint2*)(g_g2h + (size_t)s * 40 + c * 4));
    float2 f0 = __half22float2(*reinterpret_cast<__half2*>(&raw.x));
    float2 f1 = __half22float2(*reinterpret_cast<__half2*>(&raw.y));
    red_add_v4(out + (size_t)d * CDIM + c * 4,
               make_float4(f0.x * dv, f0.y * dv, f1.x * dv, f1.y * dv));
}

extern "C" void kernel_launch(void* const* d_in, const int* in_sizes, int n_in,
                              void* d_out, int out_size) {
    const float* x  = (const float*)d_in[0];
    const void*  ei = (const void*)d_in[1];
    const float* W1 = (const float*)d_in[2];
    const float* b1 = (const float*)d_in[3];
    const float* W2 = (const float*)d_in[4];
    const float* b2 = (const float*)d_in[5];

    int N = in_sizes[0] / FDIM;     // 50000
    int E = in_sizes[1] / 2;        // 800000

    void* degp = nullptr;
    cudaGetSymbolAddress(&degp, g_deg);
    cudaMemsetAsync(degp, 0, (size_t)N * sizeof(int));

    int smem1 = (128 * SXP + 64 * SWP) * sizeof(float);        // ~68 KB
    int smem2 = (128 * SX2P + 128 * SW2P) * sizeof(float);     // ~88 KB
    cudaFuncSetAttribute(gemm1_kernel, cudaFuncAttributeMaxDynamicSharedMemorySize, smem1);
    cudaFuncSetAttribute(gemm2_kernel, cudaFuncAttributeMaxDynamicSharedMemorySize, smem2);

    detect_kernel<<<1, 128>>>((const int*)ei);
    convert_kernel<<<(E + 255) / 256, 256>>>(ei, E);
    dinv_kernel<<<(N + 255) / 256, 256>>>(N);

    gemm1_kernel<<<(N + 127) / 128, 256, smem1>>>(x, W1, N);
    scatter1_kernel<<<(E + 7) / 8, 256>>>(E);

    gemm2_kernel<<<(N + 127) / 128, 256, smem2>>>(W2, (const float4*)x, b1, b2,
                                                  (float*)d_out, N);
    scatter2_kernel<<<(E * 10 + 255) / 256, 256>>>((float*)d_out, E);
}